// round 5
// baseline (speedup 1.0000x reference)
#include <cuda_runtime.h>
#include <math.h>

// ---------------- problem constants ----------------
#define BQ   8
#define LQ   128
#define TSEQ 384          // 3 * L tokens per batch
#define MTOK 3072         // BQ * TSEQ
#define DM   256          // d_model
#define DI   512          // d_inner
#define DS   16           // d_state
#define RK   16           // dt_rank
#define NL   4

// ---------------- scratch ----------------
__device__ float g_u   [MTOK * DM];
__device__ float g_res [MTOK * DM];
__device__ float g_rs2 [MTOK];          // per-row sum of squares (for rmsnorm)
__device__ float g_xz  [MTOK * 2 * DI];
__device__ float g_xc  [MTOK * DI];
__device__ float g_proj[MTOK * 48];
__device__ float g_y   [MTOK * DI];

// ---------------- embeddings + interleave -> u ; zero rs2 ----------------
__global__ void k_embed(const float* __restrict__ states,
                        const float* __restrict__ actions,
                        const float* __restrict__ goal,
                        const int*   __restrict__ timesteps,
                        const float* __restrict__ te_W,
                        const float* __restrict__ se_W, const float* __restrict__ se_b,
                        const float* __restrict__ ge_W, const float* __restrict__ ge_b,
                        const float* __restrict__ ae_W, const float* __restrict__ ae_b)
{
    int m = blockIdx.x;          // token 0..3071
    int e = threadIdx.x;         // 0..255
    if (e == 0) g_rs2[m] = 0.f;  // zero sumsq for bb_in epilogue
    int b = m / TSEQ, t = m % TSEQ;
    int slot = t % 3, l = t / 3;

    const float *inp, *Wm, *bi; int dim;
    if (slot == 0)      { inp = goal;    Wm = ge_W; bi = ge_b; dim = 6; }
    else if (slot == 1) { inp = states;  Wm = se_W; bi = se_b; dim = 6; }
    else                { inp = actions; Wm = ae_W; bi = ae_b; dim = 3; }

    float v = bi[e];
    const float* ip = inp + (size_t)(b * LQ + l) * dim;
    #pragma unroll 6
    for (int i = 0; i < dim; i++) v += ip[i] * Wm[i * DM + e];

    int ts = timesteps[b * LQ + l];
    v += te_W[(size_t)ts * DM + e];
    g_u[(size_t)m * DM + e] = v;
}

// ---------------- in_proj: 128x128 tile, 8x8/thread, rmsnorm folded ----------
// C[3072,1024] = (res * rsqrt(rs2/256+eps) * nw) @ W[256,1024]
__global__ __launch_bounds__(256)
void k_inproj(const float* __restrict__ A,
              const float* __restrict__ W,
              const float* __restrict__ nw,
              float* __restrict__ C)
{
    __shared__ float As[16][128];
    __shared__ float Ws[16][132];

    int tid = threadIdx.x;
    int bm = blockIdx.y * 128, bn = blockIdx.x * 128;
    int tx = tid & 15;        // col group: cols tx*8 .. +8
    int ty = tid >> 4;        // row group: rows ty*8 .. +8
    int arow = tid >> 2;      // 0..63
    int acol = (tid & 3) * 4; // 0,4,8,12
    int wn = tx * 8;          // W cols within tile; k-row = ty

    float s0 = rsqrtf(g_rs2[bm + arow]      * (1.f / DM) + 1e-5f);
    float s1 = rsqrtf(g_rs2[bm + arow + 64] * (1.f / DM) + 1e-5f);

    const float* Ap0 = A + (size_t)(bm + arow) * DM + acol;
    const float* Ap1 = Ap0 + (size_t)64 * DM;

    float4 pa0 = *(const float4*)(Ap0);
    float4 pa1 = *(const float4*)(Ap1);
    float4 pw0 = *(const float4*)(W + (size_t)ty * 1024 + bn + wn);
    float4 pw1 = *(const float4*)(W + (size_t)ty * 1024 + bn + wn + 4);

    float acc[8][8] = {};

    for (int k0 = 0; k0 < DM; k0 += 16) {
        __syncthreads();
        float n0 = nw[k0 + acol + 0], n1 = nw[k0 + acol + 1];
        float n2 = nw[k0 + acol + 2], n3 = nw[k0 + acol + 3];
        As[acol + 0][arow] = pa0.x * s0 * n0;
        As[acol + 1][arow] = pa0.y * s0 * n1;
        As[acol + 2][arow] = pa0.z * s0 * n2;
        As[acol + 3][arow] = pa0.w * s0 * n3;
        As[acol + 0][arow + 64] = pa1.x * s1 * n0;
        As[acol + 1][arow + 64] = pa1.y * s1 * n1;
        As[acol + 2][arow + 64] = pa1.z * s1 * n2;
        As[acol + 3][arow + 64] = pa1.w * s1 * n3;
        *(float4*)&Ws[ty][wn]     = pw0;
        *(float4*)&Ws[ty][wn + 4] = pw1;
        __syncthreads();

        if (k0 + 16 < DM) {
            pa0 = *(const float4*)(Ap0 + k0 + 16);
            pa1 = *(const float4*)(Ap1 + k0 + 16);
            pw0 = *(const float4*)(W + (size_t)(k0 + 16 + ty) * 1024 + bn + wn);
            pw1 = *(const float4*)(W + (size_t)(k0 + 16 + ty) * 1024 + bn + wn + 4);
        }

        #pragma unroll
        for (int k = 0; k < 16; k++) {
            float4 a0 = *(const float4*)&As[k][ty * 8];
            float4 a1 = *(const float4*)&As[k][ty * 8 + 4];
            float4 w0 = *(const float4*)&Ws[k][tx * 8];
            float4 w1 = *(const float4*)&Ws[k][tx * 8 + 4];
            float a[8] = {a0.x, a0.y, a0.z, a0.w, a1.x, a1.y, a1.z, a1.w};
            float w[8] = {w0.x, w0.y, w0.z, w0.w, w1.x, w1.y, w1.z, w1.w};
            #pragma unroll
            for (int i = 0; i < 8; i++)
                #pragma unroll
                for (int j = 0; j < 8; j++) acc[i][j] += a[i] * w[j];
        }
    }

    #pragma unroll
    for (int i = 0; i < 8; i++) {
        int row = bm + ty * 8 + i;
        *(float4*)&C[(size_t)row * 1024 + bn + tx * 8] =
            make_float4(acc[i][0], acc[i][1], acc[i][2], acc[i][3]);
        *(float4*)&C[(size_t)row * 1024 + bn + tx * 8 + 4] =
            make_float4(acc[i][4], acc[i][5], acc[i][6], acc[i][7]);
    }
}

// ---------------- 128x64 prefetched SGEMM, 8x4/thread, plain FFMA ------------
// EPI 0: C = acc (+bias), atomic row-sumsq into g_rs2          (bb_in)
// EPI 1: C += acc,        atomic row-sumsq into g_rs2          (out_proj)
template<int EPI>
__global__ __launch_bounds__(256)
void k_gemm128(const float* __restrict__ A, int lda,
               const float* __restrict__ W, int N, int K,
               const float* __restrict__ bias,
               float* __restrict__ C, int ldc)
{
    __shared__ float As[16][128];
    __shared__ float Ws[16][68];

    int tid = threadIdx.x;
    int bm = blockIdx.y * 128, bn = blockIdx.x * 64;
    int tx = tid & 15;        // col group (4 cols)
    int ty = tid >> 4;        // row group (8 rows)
    int arow = tid >> 2;      // 0..63
    int acol = (tid & 3) * 4; // 0,4,8,12
    int wn = tx * 4;

    const float* Ap0 = A + (size_t)(bm + arow) * lda + acol;
    const float* Ap1 = Ap0 + (size_t)64 * lda;

    float4 pa0 = *(const float4*)(Ap0);
    float4 pa1 = *(const float4*)(Ap1);
    float4 pw  = *(const float4*)(W + (size_t)ty * N + bn + wn);

    float acc[8][4] = {};

    for (int k0 = 0; k0 < K; k0 += 16) {
        __syncthreads();
        As[acol + 0][arow] = pa0.x;
        As[acol + 1][arow] = pa0.y;
        As[acol + 2][arow] = pa0.z;
        As[acol + 3][arow] = pa0.w;
        As[acol + 0][arow + 64] = pa1.x;
        As[acol + 1][arow + 64] = pa1.y;
        As[acol + 2][arow + 64] = pa1.z;
        As[acol + 3][arow + 64] = pa1.w;
        *(float4*)&Ws[ty][wn] = pw;
        __syncthreads();

        if (k0 + 16 < K) {
            pa0 = *(const float4*)(Ap0 + k0 + 16);
            pa1 = *(const float4*)(Ap1 + k0 + 16);
            pw  = *(const float4*)(W + (size_t)(k0 + 16 + ty) * N + bn + wn);
        }

        #pragma unroll
        for (int k = 0; k < 16; k++) {
            float4 a0 = *(const float4*)&As[k][ty * 8];
            float4 a1 = *(const float4*)&As[k][ty * 8 + 4];
            float4 w0 = *(const float4*)&Ws[k][tx * 4];
            float a[8] = {a0.x, a0.y, a0.z, a0.w, a1.x, a1.y, a1.z, a1.w};
            float w[4] = {w0.x, w0.y, w0.z, w0.w};
            #pragma unroll
            for (int i = 0; i < 8; i++)
                #pragma unroll
                for (int j = 0; j < 4; j++) acc[i][j] += a[i] * w[j];
        }
    }

    float rowsq[8];
    #pragma unroll
    for (int i = 0; i < 8; i++) {
        int row = bm + ty * 8 + i;
        float sq = 0.f;
        #pragma unroll
        for (int j = 0; j < 4; j++) {
            int col = bn + tx * 4 + j;
            float val = acc[i][j];
            if (EPI == 0) { if (bias) val += bias[col]; }
            else          { val += C[(size_t)row * ldc + col]; }
            C[(size_t)row * ldc + col] = val;
            sq += val * val;
        }
        rowsq[i] = sq;
    }
    #pragma unroll
    for (int o = 1; o < 16; o <<= 1)
        #pragma unroll
        for (int i = 0; i < 8; i++)
            rowsq[i] += __shfl_xor_sync(0xffffffffu, rowsq[i], o);
    if (tx == 0) {
        #pragma unroll
        for (int i = 0; i < 8; i++)
            atomicAdd(&g_rs2[bm + ty * 8 + i], rowsq[i]);
    }
}

// ---------------- 64x64 split-K SGEMM (xproj, N=48), atomic epilogue ----------
__global__ __launch_bounds__(256)
void k_xproj(const float* __restrict__ A, int lda,
             const float* __restrict__ W, int N, int Ks,
             float* __restrict__ C, int ldc)
{
    __shared__ float As[16][64];
    __shared__ float Ws[16][68];

    int tid = threadIdx.x;
    int tx = tid & 15, ty = tid >> 4;
    int bm = blockIdx.y * 64, bn = blockIdx.x * 64;
    int kb = blockIdx.z * Ks;
    int arow = tid >> 2, acol = (tid & 3) << 2;
    int wn = tx * 4;
    bool wok = (bn + wn) < N;

    const float* Arow = A + (size_t)(bm + arow) * lda + acol;
    float4 pa = *(const float4*)(Arow + kb);
    float4 pw = make_float4(0.f, 0.f, 0.f, 0.f);
    if (wok) pw = *(const float4*)(W + (size_t)(kb + ty) * N + bn + wn);

    float acc[4][4] = {};

    for (int k0 = kb; k0 < kb + Ks; k0 += 16) {
        __syncthreads();
        As[acol + 0][arow] = pa.x;
        As[acol + 1][arow] = pa.y;
        As[acol + 2][arow] = pa.z;
        As[acol + 3][arow] = pa.w;
        *(float4*)&Ws[ty][wn] = pw;
        __syncthreads();

        if (k0 + 16 < kb + Ks) {
            pa = *(const float4*)(Arow + k0 + 16);
            if (wok) pw = *(const float4*)(W + (size_t)(k0 + 16 + ty) * N + bn + wn);
        }

        #pragma unroll
        for (int k = 0; k < 16; k++) {
            float4 a0 = *(const float4*)&As[k][ty * 4];
            float4 w0 = *(const float4*)&Ws[k][tx * 4];
            float a[4] = {a0.x, a0.y, a0.z, a0.w};
            float w[4] = {w0.x, w0.y, w0.z, w0.w};
            #pragma unroll
            for (int i = 0; i < 4; i++)
                #pragma unroll
                for (int j = 0; j < 4; j++) acc[i][j] += a[i] * w[j];
        }
    }

    #pragma unroll
    for (int i = 0; i < 4; i++) {
        int row = bm + ty * 4 + i;
        #pragma unroll
        for (int j = 0; j < 4; j++) {
            int col = bn + tx * 4 + j;
            if (col < N) atomicAdd(&C[(size_t)row * ldc + col], acc[i][j]);
        }
    }
}

// ---------------- causal depthwise conv (k=4) + silu, 4 tokens/thread ----------
// Also zeroes g_proj for the split-K xproj that follows.
__global__ void k_conv(const float* __restrict__ cw, const float* __restrict__ cb)
{
    int idx = blockIdx.x * blockDim.x + threadIdx.x;  // over (MTOK/4)*(DI/4)=98304
    {
        if (idx < MTOK * 48) g_proj[idx] = 0.f;
        int i2 = idx + 98304;
        if (i2 < MTOK * 48) g_proj[i2] = 0.f;
    }
    if (idx >= (MTOK / 4) * (DI / 4)) return;
    int mg = idx / (DI / 4), dv = idx % (DI / 4);
    int d = dv * 4;
    int b = mg / (TSEQ / 4), tg = mg % (TSEQ / 4);
    int t0 = tg * 4;

    float4 win[7];
    #pragma unroll
    for (int j = 0; j < 7; j++) {
        int tt = t0 - 3 + j;
        win[j] = (tt >= 0)
            ? *(const float4*)(g_xz + (size_t)(b * TSEQ + tt) * (2 * DI) + d)
            : make_float4(0.f, 0.f, 0.f, 0.f);
    }

    float4 cw0 = *(const float4*)(cw + (d + 0) * 4);
    float4 cw1 = *(const float4*)(cw + (d + 1) * 4);
    float4 cw2 = *(const float4*)(cw + (d + 2) * 4);
    float4 cw3 = *(const float4*)(cw + (d + 3) * 4);
    float4 cb4 = *(const float4*)(cb + d);

    float cwk[4][4] = {{cw0.x, cw0.y, cw0.z, cw0.w},
                       {cw1.x, cw1.y, cw1.z, cw1.w},
                       {cw2.x, cw2.y, cw2.z, cw2.w},
                       {cw3.x, cw3.y, cw3.z, cw3.w}};

    #pragma unroll
    for (int j2 = 0; j2 < 4; j2++) {
        float4 acc = cb4;
        #pragma unroll
        for (int k = 0; k < 4; k++) {
            float4 v = win[j2 + k];
            acc.x += cwk[0][k] * v.x;
            acc.y += cwk[1][k] * v.y;
            acc.z += cwk[2][k] * v.z;
            acc.w += cwk[3][k] * v.w;
        }
        acc.x = acc.x / (1.f + __expf(-acc.x));
        acc.y = acc.y / (1.f + __expf(-acc.y));
        acc.z = acc.z / (1.f + __expf(-acc.z));
        acc.w = acc.w / (1.f + __expf(-acc.w));
        *(float4*)(g_xc + (size_t)(b * TSEQ + t0 + j2) * DI + d) = acc;
    }
}

// ---------------- selective scan, 4-way state split, fused dt-GEMM -------------
__global__ __launch_bounds__(128)
void k_scan(const float* __restrict__ A_log, const float* __restrict__ Dp,
            const float* __restrict__ dtW, const float* __restrict__ dtb)
{
    int tid = threadIdx.x;
    int sub = tid & 3;                 // state slice 0..3
    int dloc = tid >> 2;               // 0..31
    int b = blockIdx.x >> 4;
    int d = ((blockIdx.x & 15) << 5) + dloc;

    int gid = blockIdx.x * 128 + tid;
    if (gid < MTOK) g_rs2[gid] = 0.f;  // zero sumsq for out-GEMM epilogue

    float A[4], h[4] = {};
    #pragma unroll
    for (int j = 0; j < 4; j++) A[j] = -__expf(A_log[d * DS + sub * 4 + j]);

    float W16[16];
    #pragma unroll
    for (int r = 0; r < 16; r++) W16[r] = dtW[r * DI + d];
    float bd = dtb[d], Dd = Dp[d];

    __shared__ float sp[8][48];

    for (int t0 = 0; t0 < TSEQ; t0 += 8) {
        __syncthreads();
        #pragma unroll
        for (int i = 0; i < 3; i++) {
            int idx = tid + i * 128;
            int st = idx / 48, j = idx % 48;
            sp[st][j] = g_proj[((size_t)(b * TSEQ + t0 + st)) * 48 + j];
        }
        __syncthreads();

        #pragma unroll
        for (int tt = 0; tt < 8; tt++) {
            int m = b * TSEQ + t0 + tt;
            float dtr = bd;
            #pragma unroll
            for (int r = 0; r < 16; r++) dtr += sp[tt][r] * W16[r];
            float dt = (dtr > 15.f) ? dtr : log1pf(__expf(dtr));
            float x = g_xc[(size_t)m * DI + d];
            float dtx = dt * x;
            float y = 0.f;
            #pragma unroll
            for (int j = 0; j < 4; j++) {
                int n = sub * 4 + j;
                float dA = __expf(dt * A[j]);
                h[j] = dA * h[j] + dtx * sp[tt][16 + n];
                y += h[j] * sp[tt][32 + n];
            }
            y += __shfl_xor_sync(0xffffffffu, y, 1);
            y += __shfl_xor_sync(0xffffffffu, y, 2);
            if (sub == 0) {
                float z = g_xz[(size_t)m * (2 * DI) + DI + d];
                float o = (y + x * Dd) * (z / (1.f + __expf(-z)));
                g_y[(size_t)m * DI + d] = o;
            }
        }
    }
}

// ---------------- heads with fused final rmsnorm ----------------
__global__ void k_heads(const float* __restrict__ fnw,
                        const float* __restrict__ ps_W, const float* __restrict__ ps_b,
                        const float* __restrict__ pa_W, const float* __restrict__ pa_b,
                        float* __restrict__ out)
{
    int idx = blockIdx.x * blockDim.x + threadIdx.x;
    if (idx >= 6144 + 3072) return;
    if (idx < 6144) {
        int j = idx % 6; int l = (idx / 6) % LQ; int b = idx / (6 * LQ);
        int m = b * TSEQ + l * 3 + 2;   // action-slot tokens -> state preds
        float scale = rsqrtf(g_rs2[m] * (1.f / DM) + 1e-5f);
        float acc = 0.f;
        const float* f = g_res + (size_t)m * DM;
        #pragma unroll 8
        for (int e = 0; e < DM; e++) acc += f[e] * fnw[e] * ps_W[e * 6 + j];
        out[idx] = acc * scale + ps_b[j];
    } else {
        int k = idx - 6144;
        int j = k % 3; int l = (k / 3) % LQ; int b = k / (3 * LQ);
        int m = b * TSEQ + l * 3 + 1;   // state-slot tokens -> action preds
        float scale = rsqrtf(g_rs2[m] * (1.f / DM) + 1e-5f);
        float acc = 0.f;
        const float* f = g_res + (size_t)m * DM;
        #pragma unroll 8
        for (int e = 0; e < DM; e++) acc += f[e] * fnw[e] * pa_W[e * 3 + j];
        out[idx] = tanhf(acc * scale + pa_b[j]);
    }
}

// ---------------- launch ----------------
extern "C" void kernel_launch(void* const* d_in, const int* in_sizes, int n_in,
                              void* d_out, int out_size)
{
    const float* states    = (const float*)d_in[0];
    const float* actions   = (const float*)d_in[1];
    const float* goal      = (const float*)d_in[2];
    const int*   timesteps = (const int*)  d_in[3];
    const float* te_W      = (const float*)d_in[4];
    const float* se_W      = (const float*)d_in[5];
    const float* se_b      = (const float*)d_in[6];
    const float* ge_W      = (const float*)d_in[7];
    const float* ge_b      = (const float*)d_in[8];
    const float* ae_W      = (const float*)d_in[9];
    const float* ae_b      = (const float*)d_in[10];
    const float* bb_in_W   = (const float*)d_in[11];
    const float* bb_in_b   = (const float*)d_in[12];
    const float* norm_w    = (const float*)d_in[13];
    const float* in_proj_W = (const float*)d_in[14];
    const float* conv_w    = (const float*)d_in[15];
    const float* conv_b    = (const float*)d_in[16];
    const float* xproj_W   = (const float*)d_in[17];
    const float* dt_W      = (const float*)d_in[18];
    const float* dt_b      = (const float*)d_in[19];
    const float* A_log     = (const float*)d_in[20];
    const float* Dp        = (const float*)d_in[21];
    const float* out_W     = (const float*)d_in[22];
    const float* fnorm_w   = (const float*)d_in[23];
    const float* ps_W      = (const float*)d_in[24];
    const float* ps_b      = (const float*)d_in[25];
    const float* pa_W      = (const float*)d_in[26];
    const float* pa_b      = (const float*)d_in[27];
    float* out = (float*)d_out;

    float *pu, *pres, *pxz, *pxc, *pproj, *py;
    cudaGetSymbolAddress((void**)&pu,    g_u);
    cudaGetSymbolAddress((void**)&pres,  g_res);
    cudaGetSymbolAddress((void**)&pxz,   g_xz);
    cudaGetSymbolAddress((void**)&pxc,   g_xc);
    cudaGetSymbolAddress((void**)&pproj, g_proj);
    cudaGetSymbolAddress((void**)&py,    g_y);

    // 1) embeddings -> u  (also zeroes rs2)
    k_embed<<<MTOK, DM>>>(states, actions, goal, timesteps, te_W,
                          se_W, se_b, ge_W, ge_b, ae_W, ae_b);

    // 2) residual = u @ bb_in_W + b ; rs2 += row sumsq
    k_gemm128<0><<<dim3(DM / 64, MTOK / 128), 256>>>(
        pu, DM, bb_in_W, DM, DM, bb_in_b, pres, DM);

    // 3) mamba layers
    for (int i = 0; i < NL; i++) {
        const float* inW  = in_proj_W + (size_t)i * DM * 2 * DI;
        const float* cw   = conv_w    + (size_t)i * DI * 4;
        const float* cb   = conv_b    + (size_t)i * DI;
        const float* xpW  = xproj_W   + (size_t)i * DI * 48;
        const float* dtW  = dt_W      + (size_t)i * RK * DI;
        const float* dtb  = dt_b      + (size_t)i * DI;
        const float* Al   = A_log     + (size_t)i * DI * DS;
        const float* Dpi  = Dp        + (size_t)i * DI;
        const float* oW   = out_W     + (size_t)i * DI * DM;
        const float* nw   = norm_w    + (size_t)i * DM;

        // xz = rmsnorm(res; rs2, nw) @ in_W   (3072 x 1024 x 256), 128x128 tile
        k_inproj<<<dim3(1024 / 128, MTOK / 128), 256>>>(pres, inW, nw, pxz);

        // causal depthwise conv + silu -> xc ; zero proj
        k_conv<<<((MTOK / 4) * (DI / 4)) / 256, 256>>>(cw, cb);

        // proj = xc @ xproj_W  (3072 x 48 x 512), split-K x4, atomic accumulate
        k_xproj<<<dim3(1, MTOK / 64, 4), 256>>>(pxc, DI, xpW, 48, DI / 4, pproj, 48);

        // selective scan (fused dt-GEMM + softplus + gate) -> y ; zero rs2
        k_scan<<<128, 128>>>(Al, Dpi, dtW, dtb);

        // residual += y @ out_W ; rs2 += row sumsq   (3072 x 256 x 512)
        k_gemm128<1><<<dim3(DM / 64, MTOK / 128), 256>>>(
            py, DI, oW, DM, DI, nullptr, pres, DM);
    }

    // 4) heads (fused final rmsnorm)
    k_heads<<<(9216 + 255) / 256, 256>>>(fnorm_w, ps_W, ps_b, pa_W, pa_b, out);
}

// round 7
// speedup vs baseline: 1.2379x; 1.2379x over previous
#include <cuda_runtime.h>
#include <math.h>

// ---------------- problem constants ----------------
#define BQ   8
#define LQ   128
#define TSEQ 384          // 3 * L tokens per batch
#define MTOK 3072         // BQ * TSEQ
#define DM   256          // d_model
#define DI   512          // d_inner
#define DS   16           // d_state
#define RK   16           // dt_rank
#define NL   4

// ---------------- scratch (device globals; no allocation allowed) ----------------
__device__ float g_u  [MTOK * DM];
__device__ float g_res[MTOK * DM];
__device__ float g_rs [MTOK];          // per-row rmsnorm scales
__device__ float g_xz [MTOK * 2 * DI];
__device__ float g_xc [MTOK * DI];
__device__ float g_proj[MTOK * 48];
__device__ float g_y  [MTOK * DI];
__device__ float g_fin[MTOK * DM];

// ---------------- embeddings + interleave -> u ----------------
__global__ void k_embed(const float* __restrict__ states,
                        const float* __restrict__ actions,
                        const float* __restrict__ goal,
                        const int*   __restrict__ timesteps,
                        const float* __restrict__ te_W,
                        const float* __restrict__ se_W, const float* __restrict__ se_b,
                        const float* __restrict__ ge_W, const float* __restrict__ ge_b,
                        const float* __restrict__ ae_W, const float* __restrict__ ae_b)
{
    int m = blockIdx.x;          // token 0..3071
    int e = threadIdx.x;         // 0..255
    int b = m / TSEQ, t = m % TSEQ;
    int slot = t % 3, l = t / 3;

    const float *inp, *Wm, *bi; int dim;
    if (slot == 0)      { inp = goal;    Wm = ge_W; bi = ge_b; dim = 6; }
    else if (slot == 1) { inp = states;  Wm = se_W; bi = se_b; dim = 6; }
    else                { inp = actions; Wm = ae_W; bi = ae_b; dim = 3; }

    float v = bi[e];
    const float* ip = inp + (size_t)(b * LQ + l) * dim;
    #pragma unroll 6
    for (int i = 0; i < dim; i++) v += ip[i] * Wm[i * DM + e];

    int ts = timesteps[b * LQ + l];
    v += te_W[(size_t)ts * DM + e];
    g_u[(size_t)m * DM + e] = v;
}

// ---------------- per-row rmsnorm scale: rs[m] = rsqrt(mean(x^2)+eps) ----------------
__global__ void k_rowscale(const float* __restrict__ in, float* __restrict__ rs)
{
    int warp = blockIdx.x * 8 + (threadIdx.x >> 5);
    int lane = threadIdx.x & 31;
    const float4* p = (const float4*)(in + (size_t)warp * DM);
    float s = 0.f;
    #pragma unroll
    for (int i = lane; i < DM / 4; i += 32) {
        float4 v = p[i];
        s += v.x * v.x + v.y * v.y + v.z * v.z + v.w * v.w;
    }
    #pragma unroll
    for (int o = 16; o > 0; o >>= 1) s += __shfl_down_sync(0xffffffffu, s, o);
    if (lane == 0) rs[warp] = rsqrtf(s * (1.0f / DM) + 1e-5f);
}

// ---------------- full rmsnorm (final norm only) ----------------
__global__ void k_rmsnorm(const float* __restrict__ in,
                          const float* __restrict__ w,
                          float* __restrict__ out)
{
    int m = blockIdx.x, e = threadIdx.x;
    float x = in[(size_t)m * DM + e];
    float s = x * x;
    #pragma unroll
    for (int o = 16; o > 0; o >>= 1) s += __shfl_down_sync(0xffffffffu, s, o);
    __shared__ float ws[8];
    if ((e & 31) == 0) ws[e >> 5] = s;
    __syncthreads();
    if (e < 8) {
        float t = ws[e];
        #pragma unroll
        for (int o = 4; o > 0; o >>= 1) t += __shfl_down_sync(0xffu, t, o);
        if (e == 0) ws[0] = t;
    }
    __syncthreads();
    float scale = rsqrtf(ws[0] * (1.0f / DM) + 1e-5f);
    out[(size_t)m * DM + e] = x * scale * w[e];
}

// ---------------- 128x64x16 SGEMM, 8x4 per thread, float4 everywhere ----------------
// C[M,N] = A'[M,K] @ W[K,N]  where A' = A (NORM=false) or A * rs[m] * nw[k] (NORM=true)
// EPI: 0 = store (+bias if non-null), 1 = accumulate into C
template<int EPI, bool NORM>
__global__ __launch_bounds__(256)
void k_gemm128(const float* __restrict__ A, int lda,
               const float* __restrict__ W, int N, int K,
               const float* __restrict__ bias,
               const float* __restrict__ rs,
               const float* __restrict__ nw,
               float* __restrict__ C, int ldc)
{
    __shared__ float As[16][128];
    __shared__ float Ws[16][68];

    int tid = threadIdx.x;
    int bm = blockIdx.y * 128, bn = blockIdx.x * 64;
    int tx = tid & 15;       // col group -> cols tx*4 .. +4
    int ty = tid >> 4;       // row group -> rows ty*8 .. +8

    int arow = tid >> 2;            // 0..63
    int acol = (tid & 3) * 4;       // 0,4,8,12
    int wk = tid >> 4, wn = (tid & 15) * 4;

    float s0 = 1.f, s1 = 1.f;
    if (NORM) {
        s0 = rs[bm + arow];
        s1 = rs[bm + arow + 64];
    }

    const float* Ap0 = A + (size_t)(bm + arow) * lda + acol;
    const float* Ap1 = Ap0 + (size_t)64 * lda;

    float4 pa0 = *(const float4*)(Ap0);
    float4 pa1 = *(const float4*)(Ap1);
    float4 pw  = *(const float4*)(W + (size_t)wk * N + bn + wn);

    float acc[8][4] = {};

    for (int k0 = 0; k0 < K; k0 += 16) {
        __syncthreads();
        if (NORM) {
            float n0 = nw[k0 + acol + 0], n1 = nw[k0 + acol + 1];
            float n2 = nw[k0 + acol + 2], n3 = nw[k0 + acol + 3];
            As[acol + 0][arow] = pa0.x * s0 * n0;
            As[acol + 1][arow] = pa0.y * s0 * n1;
            As[acol + 2][arow] = pa0.z * s0 * n2;
            As[acol + 3][arow] = pa0.w * s0 * n3;
            As[acol + 0][arow + 64] = pa1.x * s1 * n0;
            As[acol + 1][arow + 64] = pa1.y * s1 * n1;
            As[acol + 2][arow + 64] = pa1.z * s1 * n2;
            As[acol + 3][arow + 64] = pa1.w * s1 * n3;
        } else {
            As[acol + 0][arow] = pa0.x;
            As[acol + 1][arow] = pa0.y;
            As[acol + 2][arow] = pa0.z;
            As[acol + 3][arow] = pa0.w;
            As[acol + 0][arow + 64] = pa1.x;
            As[acol + 1][arow + 64] = pa1.y;
            As[acol + 2][arow + 64] = pa1.z;
            As[acol + 3][arow + 64] = pa1.w;
        }
        *(float4*)&Ws[wk][wn] = pw;
        __syncthreads();

        if (k0 + 16 < K) {
            pa0 = *(const float4*)(Ap0 + k0 + 16);
            pa1 = *(const float4*)(Ap1 + k0 + 16);
            pw  = *(const float4*)(W + (size_t)(k0 + 16 + wk) * N + bn + wn);
        }

        #pragma unroll
        for (int k = 0; k < 16; k++) {
            float4 a0 = *(const float4*)&As[k][ty * 8];
            float4 a1 = *(const float4*)&As[k][ty * 8 + 4];
            float4 w0 = *(const float4*)&Ws[k][tx * 4];
            float a[8] = {a0.x, a0.y, a0.z, a0.w, a1.x, a1.y, a1.z, a1.w};
            float w[4] = {w0.x, w0.y, w0.z, w0.w};
            #pragma unroll
            for (int i = 0; i < 8; i++)
                #pragma unroll
                for (int j = 0; j < 4; j++) acc[i][j] += a[i] * w[j];
        }
    }

    #pragma unroll
    for (int i = 0; i < 8; i++) {
        int row = bm + ty * 8 + i;
        #pragma unroll
        for (int j = 0; j < 4; j++) {
            int col = bn + tx * 4 + j;
            float v = acc[i][j];
            if (EPI == 0) {
                if (bias) v += bias[col];
                C[(size_t)row * ldc + col] = v;
            } else {
                C[(size_t)row * ldc + col] += v;
            }
        }
    }
}

// ---------------- 64x64 split-K SGEMM (xproj, N=48), atomic epilogue ----------
__global__ __launch_bounds__(256)
void k_xproj(const float* __restrict__ A, int lda,
             const float* __restrict__ W, int N, int Ks,
             float* __restrict__ C, int ldc)
{
    __shared__ float As[16][64];
    __shared__ float Ws[16][68];

    int tid = threadIdx.x;
    int tx = tid & 15, ty = tid >> 4;
    int bm = blockIdx.y * 64, bn = blockIdx.x * 64;
    int kb = blockIdx.z * Ks;
    int arow = tid >> 2, acol = (tid & 3) << 2;
    int wn = tx * 4;
    bool wok = (bn + wn) < N;

    const float* Arow = A + (size_t)(bm + arow) * lda + acol;
    float4 pa = *(const float4*)(Arow + kb);
    float4 pw = make_float4(0.f, 0.f, 0.f, 0.f);
    if (wok) pw = *(const float4*)(W + (size_t)(kb + ty) * N + bn + wn);

    float acc[4][4] = {};

    for (int k0 = kb; k0 < kb + Ks; k0 += 16) {
        __syncthreads();
        As[acol + 0][arow] = pa.x;
        As[acol + 1][arow] = pa.y;
        As[acol + 2][arow] = pa.z;
        As[acol + 3][arow] = pa.w;
        *(float4*)&Ws[ty][wn] = pw;
        __syncthreads();

        if (k0 + 16 < kb + Ks) {
            pa = *(const float4*)(Arow + k0 + 16);
            if (wok) pw = *(const float4*)(W + (size_t)(k0 + 16 + ty) * N + bn + wn);
        }

        #pragma unroll
        for (int k = 0; k < 16; k++) {
            float4 a0 = *(const float4*)&As[k][ty * 4];
            float4 w0 = *(const float4*)&Ws[k][tx * 4];
            float a[4] = {a0.x, a0.y, a0.z, a0.w};
            float w[4] = {w0.x, w0.y, w0.z, w0.w};
            #pragma unroll
            for (int i = 0; i < 4; i++)
                #pragma unroll
                for (int j = 0; j < 4; j++) acc[i][j] += a[i] * w[j];
        }
    }

    #pragma unroll
    for (int i = 0; i < 4; i++) {
        int row = bm + ty * 4 + i;
        #pragma unroll
        for (int j = 0; j < 4; j++) {
            int col = bn + tx * 4 + j;
            if (col < N) atomicAdd(&C[(size_t)row * ldc + col], acc[i][j]);
        }
    }
}

// ---------------- causal depthwise conv (k=4) + silu, 4 tokens/thread ----------
// Also zeroes g_proj for the split-K xproj that follows.
__global__ void k_conv(const float* __restrict__ cw, const float* __restrict__ cb)
{
    int idx = blockIdx.x * blockDim.x + threadIdx.x;  // over (MTOK/4)*(DI/4)=98304
    {
        if (idx < MTOK * 48) g_proj[idx] = 0.f;
        int i2 = idx + 98304;
        if (i2 < MTOK * 48) g_proj[i2] = 0.f;
    }
    if (idx >= (MTOK / 4) * (DI / 4)) return;
    int mg = idx / (DI / 4), dv = idx % (DI / 4);
    int d = dv * 4;
    int b = mg / (TSEQ / 4), tg = mg % (TSEQ / 4);
    int t0 = tg * 4;

    float4 win[7];
    #pragma unroll
    for (int j = 0; j < 7; j++) {
        int tt = t0 - 3 + j;
        win[j] = (tt >= 0)
            ? *(const float4*)(g_xz + (size_t)(b * TSEQ + tt) * (2 * DI) + d)
            : make_float4(0.f, 0.f, 0.f, 0.f);
    }

    float4 cw0 = *(const float4*)(cw + (d + 0) * 4);
    float4 cw1 = *(const float4*)(cw + (d + 1) * 4);
    float4 cw2 = *(const float4*)(cw + (d + 2) * 4);
    float4 cw3 = *(const float4*)(cw + (d + 3) * 4);
    float4 cb4 = *(const float4*)(cb + d);

    float cwk[4][4] = {{cw0.x, cw0.y, cw0.z, cw0.w},
                       {cw1.x, cw1.y, cw1.z, cw1.w},
                       {cw2.x, cw2.y, cw2.z, cw2.w},
                       {cw3.x, cw3.y, cw3.z, cw3.w}};

    #pragma unroll
    for (int j2 = 0; j2 < 4; j2++) {
        float4 acc = cb4;
        #pragma unroll
        for (int k = 0; k < 4; k++) {
            float4 v = win[j2 + k];
            acc.x += cwk[0][k] * v.x;
            acc.y += cwk[1][k] * v.y;
            acc.z += cwk[2][k] * v.z;
            acc.w += cwk[3][k] * v.w;
        }
        acc.x = acc.x / (1.f + __expf(-acc.x));
        acc.y = acc.y / (1.f + __expf(-acc.y));
        acc.z = acc.z / (1.f + __expf(-acc.z));
        acc.w = acc.w / (1.f + __expf(-acc.w));
        *(float4*)(g_xc + (size_t)(b * TSEQ + t0 + j2) * DI + d) = acc;
    }
}

// ---------------- selective scan: R2 shape (64 blocks x 64 thr), fused dt -----
__global__ __launch_bounds__(64)
void k_scan(const float* __restrict__ A_log, const float* __restrict__ Dp,
            const float* __restrict__ dtW, const float* __restrict__ dtb)
{
    int b = blockIdx.x >> 3;                          // batch
    int d = ((blockIdx.x & 7) << 6) + threadIdx.x;    // 0..511

    float A[16], h[16];
    #pragma unroll
    for (int n = 0; n < 16; n++) {
        A[n] = -__expf(A_log[d * 16 + n]);
        h[n] = 0.f;
    }
    float W16[16];
    #pragma unroll
    for (int r = 0; r < 16; r++) W16[r] = dtW[r * DI + d];
    float bd = dtb[d], Dd = Dp[d];

    __shared__ float sp[8][48];   // 8 steps of (dt_in[16], B[16], C[16])

    for (int t0 = 0; t0 < TSEQ; t0 += 8) {
        __syncthreads();
        int i0 = threadIdx.x * 6;                     // 64*6 = 384 floats
        #pragma unroll
        for (int i = 0; i < 6; i++) {
            int idx = i0 + i; int st = idx / 48, j = idx % 48;
            sp[st][j] = g_proj[((size_t)(b * TSEQ + t0 + st)) * 48 + j];
        }
        __syncthreads();

        #pragma unroll
        for (int tt = 0; tt < 8; tt++) {
            int m = b * TSEQ + t0 + tt;
            float dtr = bd;
            #pragma unroll
            for (int r = 0; r < 16; r++) dtr += sp[tt][r] * W16[r];
            float dt = (dtr > 15.f) ? dtr : log1pf(__expf(dtr));
            float x = g_xc[(size_t)m * DI + d];
            float dtx = dt * x;
            float y = 0.f;
            #pragma unroll
            for (int n = 0; n < 16; n++) {
                float dA = __expf(dt * A[n]);
                h[n] = dA * h[n] + dtx * sp[tt][16 + n];
                y += h[n] * sp[tt][32 + n];
            }
            float z = g_xz[(size_t)m * (2 * DI) + DI + d];
            float o = (y + x * Dd) * (z / (1.f + __expf(-z)));
            g_y[(size_t)m * DI + d] = o;
        }
    }
}

// ---------------- output heads ----------------
__global__ void k_heads(const float* __restrict__ ps_W, const float* __restrict__ ps_b,
                        const float* __restrict__ pa_W, const float* __restrict__ pa_b,
                        float* __restrict__ out)
{
    int idx = blockIdx.x * blockDim.x + threadIdx.x;
    if (idx >= 6144 + 3072) return;
    if (idx < 6144) {
        int j = idx % 6; int l = (idx / 6) % LQ; int b = idx / (6 * LQ);
        int m = b * TSEQ + l * 3 + 2;
        float acc = ps_b[j];
        const float* f = g_fin + (size_t)m * DM;
        #pragma unroll 8
        for (int e = 0; e < DM; e++) acc += f[e] * ps_W[e * 6 + j];
        out[idx] = acc;
    } else {
        int k = idx - 6144;
        int j = k % 3; int l = (k / 3) % LQ; int b = k / (3 * LQ);
        int m = b * TSEQ + l * 3 + 1;
        float acc = pa_b[j];
        const float* f = g_fin + (size_t)m * DM;
        #pragma unroll 8
        for (int e = 0; e < DM; e++) acc += f[e] * pa_W[e * 3 + j];
        out[idx] = tanhf(acc);
    }
}

// ---------------- launch ----------------
extern "C" void kernel_launch(void* const* d_in, const int* in_sizes, int n_in,
                              void* d_out, int out_size)
{
    const float* states    = (const float*)d_in[0];
    const float* actions   = (const float*)d_in[1];
    const float* goal      = (const float*)d_in[2];
    const int*   timesteps = (const int*)  d_in[3];
    const float* te_W      = (const float*)d_in[4];
    const float* se_W      = (const float*)d_in[5];
    const float* se_b      = (const float*)d_in[6];
    const float* ge_W      = (const float*)d_in[7];
    const float* ge_b      = (const float*)d_in[8];
    const float* ae_W      = (const float*)d_in[9];
    const float* ae_b      = (const float*)d_in[10];
    const float* bb_in_W   = (const float*)d_in[11];
    const float* bb_in_b   = (const float*)d_in[12];
    const float* norm_w    = (const float*)d_in[13];
    const float* in_proj_W = (const float*)d_in[14];
    const float* conv_w    = (const float*)d_in[15];
    const float* conv_b    = (const float*)d_in[16];
    const float* xproj_W   = (const float*)d_in[17];
    const float* dt_W      = (const float*)d_in[18];
    const float* dt_b      = (const float*)d_in[19];
    const float* A_log     = (const float*)d_in[20];
    const float* Dp        = (const float*)d_in[21];
    const float* out_W     = (const float*)d_in[22];
    const float* fnorm_w   = (const float*)d_in[23];
    const float* ps_W      = (const float*)d_in[24];
    const float* ps_b      = (const float*)d_in[25];
    const float* pa_W      = (const float*)d_in[26];
    const float* pa_b      = (const float*)d_in[27];
    float* out = (float*)d_out;

    float *pu, *pres, *prs, *pxz, *pxc, *pproj, *py, *pfin;
    cudaGetSymbolAddress((void**)&pu,    g_u);
    cudaGetSymbolAddress((void**)&pres,  g_res);
    cudaGetSymbolAddress((void**)&prs,   g_rs);
    cudaGetSymbolAddress((void**)&pxz,   g_xz);
    cudaGetSymbolAddress((void**)&pxc,   g_xc);
    cudaGetSymbolAddress((void**)&pproj, g_proj);
    cudaGetSymbolAddress((void**)&py,    g_y);
    cudaGetSymbolAddress((void**)&pfin,  g_fin);

    // 1) embeddings -> u
    k_embed<<<MTOK, DM>>>(states, actions, goal, timesteps, te_W,
                          se_W, se_b, ge_W, ge_b, ae_W, ae_b);

    // 2) residual = u @ bb_in_W + bb_in_b   (3072 x 256 x 256)
    k_gemm128<0, false><<<dim3(DM / 64, MTOK / 128), 256>>>(
        pu, DM, bb_in_W, DM, DM, bb_in_b, nullptr, nullptr, pres, DM);

    // 3) mamba layers
    for (int i = 0; i < NL; i++) {
        const float* inW  = in_proj_W + (size_t)i * DM * 2 * DI;
        const float* cw   = conv_w    + (size_t)i * DI * 4;
        const float* cb   = conv_b    + (size_t)i * DI;
        const float* xpW  = xproj_W   + (size_t)i * DI * 48;
        const float* dtW  = dt_W      + (size_t)i * RK * DI;
        const float* dtb  = dt_b      + (size_t)i * DI;
        const float* Al   = A_log     + (size_t)i * DI * DS;
        const float* Dpi  = Dp        + (size_t)i * DI;
        const float* oW   = out_W     + (size_t)i * DI * DM;
        const float* nw   = norm_w    + (size_t)i * DM;

        // rmsnorm row scales
        k_rowscale<<<MTOK / 8, 256>>>(pres, prs);

        // xz = rmsnorm(res) @ in_W   (3072 x 1024 x 256), norm folded into A-load
        k_gemm128<0, true><<<dim3(2 * DI / 64, MTOK / 128), 256>>>(
            pres, DM, inW, 2 * DI, DM, nullptr, prs, nw, pxz, 2 * DI);

        // causal depthwise conv + silu -> xc ; zero proj
        k_conv<<<((MTOK / 4) * (DI / 4)) / 256, 256>>>(cw, cb);

        // proj = xc @ xproj_W  (3072 x 48 x 512), split-K x4, atomic accumulate
        k_xproj<<<dim3(1, MTOK / 64, 4), 256>>>(pxc, DI, xpW, 48, DI / 4, pproj, 48);

        // selective scan (fused dt-GEMM + softplus + gate) -> y
        k_scan<<<BQ * 8, 64>>>(Al, Dpi, dtW, dtb);

        // residual += y @ out_W   (3072 x 256 x 512)
        k_gemm128<1, false><<<dim3(DM / 64, MTOK / 128), 256>>>(
            py, DI, oW, DM, DI, nullptr, nullptr, nullptr, pres, DM);
    }

    // 4) final norm + heads
    k_rmsnorm<<<MTOK, DM>>>(pres, fnorm_w, pfin);
    k_heads<<<(9216 + 255) / 256, 256>>>(ps_W, ps_b, pa_W, pa_b, out);
}

// round 8
// speedup vs baseline: 1.6747x; 1.3529x over previous
#include <cuda_runtime.h>
#include <math.h>

// ---------------- problem constants ----------------
#define BQ   8
#define LQ   128
#define TSEQ 384          // 3 * L tokens per batch
#define MTOK 3072         // BQ * TSEQ
#define DM   256          // d_model
#define DI   512          // d_inner
#define DS   16           // d_state
#define RK   16           // dt_rank
#define NL   4

// ---------------- scratch (device globals; no allocation allowed) ----------------
__device__ float g_u  [MTOK * DM];
__device__ float g_res[MTOK * DM];
__device__ float g_rs [MTOK];          // per-row rmsnorm scales
__device__ float g_xz [MTOK * 2 * DI];
__device__ float g_xc [MTOK * DI];
__device__ float g_proj[MTOK * 48];
__device__ float g_y  [MTOK * DI];
__device__ float g_fin[MTOK * DM];

// ---------------- embeddings + interleave -> u ----------------
__global__ void k_embed(const float* __restrict__ states,
                        const float* __restrict__ actions,
                        const float* __restrict__ goal,
                        const int*   __restrict__ timesteps,
                        const float* __restrict__ te_W,
                        const float* __restrict__ se_W, const float* __restrict__ se_b,
                        const float* __restrict__ ge_W, const float* __restrict__ ge_b,
                        const float* __restrict__ ae_W, const float* __restrict__ ae_b)
{
    int m = blockIdx.x;          // token 0..3071
    int e = threadIdx.x;         // 0..255
    int b = m / TSEQ, t = m % TSEQ;
    int slot = t % 3, l = t / 3;

    const float *inp, *Wm, *bi; int dim;
    if (slot == 0)      { inp = goal;    Wm = ge_W; bi = ge_b; dim = 6; }
    else if (slot == 1) { inp = states;  Wm = se_W; bi = se_b; dim = 6; }
    else                { inp = actions; Wm = ae_W; bi = ae_b; dim = 3; }

    float v = bi[e];
    const float* ip = inp + (size_t)(b * LQ + l) * dim;
    #pragma unroll 6
    for (int i = 0; i < dim; i++) v += ip[i] * Wm[i * DM + e];

    int ts = timesteps[b * LQ + l];
    v += te_W[(size_t)ts * DM + e];
    g_u[(size_t)m * DM + e] = v;
}

// ---------------- per-row rmsnorm scale: rs[m] = rsqrt(mean(x^2)+eps) ----------------
__global__ void k_rowscale(const float* __restrict__ in, float* __restrict__ rs)
{
    int warp = blockIdx.x * 8 + (threadIdx.x >> 5);
    int lane = threadIdx.x & 31;
    const float4* p = (const float4*)(in + (size_t)warp * DM);
    float s = 0.f;
    #pragma unroll
    for (int i = lane; i < DM / 4; i += 32) {
        float4 v = p[i];
        s += v.x * v.x + v.y * v.y + v.z * v.z + v.w * v.w;
    }
    #pragma unroll
    for (int o = 16; o > 0; o >>= 1) s += __shfl_down_sync(0xffffffffu, s, o);
    if (lane == 0) rs[warp] = rsqrtf(s * (1.0f / DM) + 1e-5f);
}

// ---------------- full rmsnorm (final norm only) ----------------
__global__ void k_rmsnorm(const float* __restrict__ in,
                          const float* __restrict__ w,
                          float* __restrict__ out)
{
    int m = blockIdx.x, e = threadIdx.x;
    float x = in[(size_t)m * DM + e];
    float s = x * x;
    #pragma unroll
    for (int o = 16; o > 0; o >>= 1) s += __shfl_down_sync(0xffffffffu, s, o);
    __shared__ float ws[8];
    if ((e & 31) == 0) ws[e >> 5] = s;
    __syncthreads();
    if (e < 8) {
        float t = ws[e];
        #pragma unroll
        for (int o = 4; o > 0; o >>= 1) t += __shfl_down_sync(0xffu, t, o);
        if (e == 0) ws[0] = t;
    }
    __syncthreads();
    float scale = rsqrtf(ws[0] * (1.0f / DM) + 1e-5f);
    out[(size_t)m * DM + e] = x * scale * w[e];
}

// ---------------- 128x64x16 SGEMM, 8x4 per thread, float4 everywhere ----------------
// C[M,N] = A'[M,K] @ W[K,N]  where A' = A (NORM=false) or A * rs[m] * nw[k] (NORM=true)
// EPI: 0 = store (+bias if non-null), 1 = accumulate into C, 2 = atomicAdd (split-K)
// K is the K-slice length; blockIdx.z selects the slice.
template<int EPI, bool NORM>
__global__ __launch_bounds__(256)
void k_gemm128(const float* __restrict__ A, int lda,
               const float* __restrict__ W, int N, int K,
               const float* __restrict__ bias,
               const float* __restrict__ rs,
               const float* __restrict__ nw,
               float* __restrict__ C, int ldc)
{
    __shared__ float As[16][128];
    __shared__ float Ws[16][68];

    int tid = threadIdx.x;
    int bm = blockIdx.y * 128, bn = blockIdx.x * 64;
    int kb = blockIdx.z * K;
    int tx = tid & 15;       // col group -> cols tx*4 .. +4
    int ty = tid >> 4;       // row group -> rows ty*8 .. +8

    int arow = tid >> 2;            // 0..63
    int acol = (tid & 3) * 4;       // 0,4,8,12
    int wk = tid >> 4, wn = (tid & 15) * 4;

    float s0 = 1.f, s1 = 1.f;
    if (NORM) {
        s0 = rs[bm + arow];
        s1 = rs[bm + arow + 64];
    }

    const float* Ap0 = A + (size_t)(bm + arow) * lda + kb + acol;
    const float* Ap1 = Ap0 + (size_t)64 * lda;

    float4 pa0 = *(const float4*)(Ap0);
    float4 pa1 = *(const float4*)(Ap1);
    float4 pw  = *(const float4*)(W + (size_t)(kb + wk) * N + bn + wn);

    float acc[8][4] = {};

    for (int k0 = 0; k0 < K; k0 += 16) {
        __syncthreads();
        if (NORM) {
            float n0 = nw[k0 + acol + 0], n1 = nw[k0 + acol + 1];
            float n2 = nw[k0 + acol + 2], n3 = nw[k0 + acol + 3];
            As[acol + 0][arow] = pa0.x * s0 * n0;
            As[acol + 1][arow] = pa0.y * s0 * n1;
            As[acol + 2][arow] = pa0.z * s0 * n2;
            As[acol + 3][arow] = pa0.w * s0 * n3;
            As[acol + 0][arow + 64] = pa1.x * s1 * n0;
            As[acol + 1][arow + 64] = pa1.y * s1 * n1;
            As[acol + 2][arow + 64] = pa1.z * s1 * n2;
            As[acol + 3][arow + 64] = pa1.w * s1 * n3;
        } else {
            As[acol + 0][arow] = pa0.x;
            As[acol + 1][arow] = pa0.y;
            As[acol + 2][arow] = pa0.z;
            As[acol + 3][arow] = pa0.w;
            As[acol + 0][arow + 64] = pa1.x;
            As[acol + 1][arow + 64] = pa1.y;
            As[acol + 2][arow + 64] = pa1.z;
            As[acol + 3][arow + 64] = pa1.w;
        }
        *(float4*)&Ws[wk][wn] = pw;
        __syncthreads();

        if (k0 + 16 < K) {
            pa0 = *(const float4*)(Ap0 + k0 + 16);
            pa1 = *(const float4*)(Ap1 + k0 + 16);
            pw  = *(const float4*)(W + (size_t)(kb + k0 + 16 + wk) * N + bn + wn);
        }

        #pragma unroll
        for (int k = 0; k < 16; k++) {
            float4 a0 = *(const float4*)&As[k][ty * 8];
            float4 a1 = *(const float4*)&As[k][ty * 8 + 4];
            float4 w0 = *(const float4*)&Ws[k][tx * 4];
            float a[8] = {a0.x, a0.y, a0.z, a0.w, a1.x, a1.y, a1.z, a1.w};
            float w[4] = {w0.x, w0.y, w0.z, w0.w};
            #pragma unroll
            for (int i = 0; i < 8; i++)
                #pragma unroll
                for (int j = 0; j < 4; j++) acc[i][j] += a[i] * w[j];
        }
    }

    #pragma unroll
    for (int i = 0; i < 8; i++) {
        int row = bm + ty * 8 + i;
        #pragma unroll
        for (int j = 0; j < 4; j++) {
            int col = bn + tx * 4 + j;
            float v = acc[i][j];
            if (EPI == 0) {
                if (bias) v += bias[col];
                C[(size_t)row * ldc + col] = v;
            } else if (EPI == 1) {
                C[(size_t)row * ldc + col] += v;
            } else {
                atomicAdd(&C[(size_t)row * ldc + col], v);
            }
        }
    }
}

// ---------------- 64x64 split-K SGEMM (xproj, N=48), atomic epilogue ----------
__global__ __launch_bounds__(256)
void k_xproj(const float* __restrict__ A, int lda,
             const float* __restrict__ W, int N, int Ks,
             float* __restrict__ C, int ldc)
{
    __shared__ float As[16][64];
    __shared__ float Ws[16][68];

    int tid = threadIdx.x;
    int tx = tid & 15, ty = tid >> 4;
    int bm = blockIdx.y * 64, bn = blockIdx.x * 64;
    int kb = blockIdx.z * Ks;
    int arow = tid >> 2, acol = (tid & 3) << 2;
    int wn = tx * 4;
    bool wok = (bn + wn) < N;

    const float* Arow = A + (size_t)(bm + arow) * lda + acol;
    float4 pa = *(const float4*)(Arow + kb);
    float4 pw = make_float4(0.f, 0.f, 0.f, 0.f);
    if (wok) pw = *(const float4*)(W + (size_t)(kb + ty) * N + bn + wn);

    float acc[4][4] = {};

    for (int k0 = kb; k0 < kb + Ks; k0 += 16) {
        __syncthreads();
        As[acol + 0][arow] = pa.x;
        As[acol + 1][arow] = pa.y;
        As[acol + 2][arow] = pa.z;
        As[acol + 3][arow] = pa.w;
        *(float4*)&Ws[ty][wn] = pw;
        __syncthreads();

        if (k0 + 16 < kb + Ks) {
            pa = *(const float4*)(Arow + k0 + 16);
            if (wok) pw = *(const float4*)(W + (size_t)(k0 + 16 + ty) * N + bn + wn);
        }

        #pragma unroll
        for (int k = 0; k < 16; k++) {
            float4 a0 = *(const float4*)&As[k][ty * 4];
            float4 w0 = *(const float4*)&Ws[k][tx * 4];
            float a[4] = {a0.x, a0.y, a0.z, a0.w};
            float w[4] = {w0.x, w0.y, w0.z, w0.w};
            #pragma unroll
            for (int i = 0; i < 4; i++)
                #pragma unroll
                for (int j = 0; j < 4; j++) acc[i][j] += a[i] * w[j];
        }
    }

    #pragma unroll
    for (int i = 0; i < 4; i++) {
        int row = bm + ty * 4 + i;
        #pragma unroll
        for (int j = 0; j < 4; j++) {
            int col = bn + tx * 4 + j;
            if (col < N) atomicAdd(&C[(size_t)row * ldc + col], acc[i][j]);
        }
    }
}

// ---------------- causal depthwise conv (k=4) + silu, 4 tokens/thread ----------
// Also zeroes g_proj for the split-K xproj that follows.
__global__ void k_conv(const float* __restrict__ cw, const float* __restrict__ cb)
{
    int idx = blockIdx.x * blockDim.x + threadIdx.x;  // over (MTOK/4)*(DI/4)=98304
    {
        if (idx < MTOK * 48) g_proj[idx] = 0.f;
        int i2 = idx + 98304;
        if (i2 < MTOK * 48) g_proj[i2] = 0.f;
    }
    if (idx >= (MTOK / 4) * (DI / 4)) return;
    int mg = idx / (DI / 4), dv = idx % (DI / 4);
    int d = dv * 4;
    int b = mg / (TSEQ / 4), tg = mg % (TSEQ / 4);
    int t0 = tg * 4;

    float4 win[7];
    #pragma unroll
    for (int j = 0; j < 7; j++) {
        int tt = t0 - 3 + j;
        win[j] = (tt >= 0)
            ? *(const float4*)(g_xz + (size_t)(b * TSEQ + tt) * (2 * DI) + d)
            : make_float4(0.f, 0.f, 0.f, 0.f);
    }

    float4 cw0 = *(const float4*)(cw + (d + 0) * 4);
    float4 cw1 = *(const float4*)(cw + (d + 1) * 4);
    float4 cw2 = *(const float4*)(cw + (d + 2) * 4);
    float4 cw3 = *(const float4*)(cw + (d + 3) * 4);
    float4 cb4 = *(const float4*)(cb + d);

    float cwk[4][4] = {{cw0.x, cw0.y, cw0.z, cw0.w},
                       {cw1.x, cw1.y, cw1.z, cw1.w},
                       {cw2.x, cw2.y, cw2.z, cw2.w},
                       {cw3.x, cw3.y, cw3.z, cw3.w}};

    #pragma unroll
    for (int j2 = 0; j2 < 4; j2++) {
        float4 acc = cb4;
        #pragma unroll
        for (int k = 0; k < 4; k++) {
            float4 v = win[j2 + k];
            acc.x += cwk[0][k] * v.x;
            acc.y += cwk[1][k] * v.y;
            acc.z += cwk[2][k] * v.z;
            acc.w += cwk[3][k] * v.w;
        }
        acc.x = acc.x / (1.f + __expf(-acc.x));
        acc.y = acc.y / (1.f + __expf(-acc.y));
        acc.z = acc.z / (1.f + __expf(-acc.z));
        acc.w = acc.w / (1.f + __expf(-acc.w));
        *(float4*)(g_xc + (size_t)(b * TSEQ + t0 + j2) * DI + d) = acc;
    }
}

// ---------------- selective scan: 64 blocks x 64 thr, fused dt, prefetch ------
__global__ __launch_bounds__(64)
void k_scan(const float* __restrict__ A_log, const float* __restrict__ Dp,
            const float* __restrict__ dtW, const float* __restrict__ dtb)
{
    int b = blockIdx.x >> 3;                          // batch
    int d = ((blockIdx.x & 7) << 6) + threadIdx.x;    // 0..511

    float A[16], h[16];
    #pragma unroll
    for (int n = 0; n < 16; n++) {
        A[n] = -__expf(A_log[d * 16 + n]);
        h[n] = 0.f;
    }
    // Detect linear spectrum A[n] = (n+1)*A[0]  (true for this model's A_log).
    float A0 = A[0];
    bool lin = true;
    #pragma unroll
    for (int n = 0; n < 16; n++)
        lin = lin && (fabsf(A[n] - (float)(n + 1) * A0) <= 1e-4f * fabsf(A[n]));

    float W16[16];
    #pragma unroll
    for (int r = 0; r < 16; r++) W16[r] = dtW[r * DI + d];
    float bd = dtb[d], Dd = Dp[d];

    __shared__ float sp[8][48];   // 8 steps of (dt_in[16], B[16], C[16])

    for (int t0 = 0; t0 < TSEQ; t0 += 8) {
        __syncthreads();
        int i0 = threadIdx.x * 6;                     // 64*6 = 384 floats
        #pragma unroll
        for (int i = 0; i < 6; i++) {
            int idx = i0 + i; int st = idx / 48, j = idx % 48;
            sp[st][j] = g_proj[((size_t)(b * TSEQ + t0 + st)) * 48 + j];
        }
        // batch-prefetch xc and z for the 8 steps (16 independent loads)
        float xc8[8], z8[8];
        #pragma unroll
        for (int i = 0; i < 8; i++)
            xc8[i] = g_xc[(size_t)(b * TSEQ + t0 + i) * DI + d];
        #pragma unroll
        for (int i = 0; i < 8; i++)
            z8[i] = g_xz[(size_t)(b * TSEQ + t0 + i) * (2 * DI) + DI + d];
        __syncthreads();

        #pragma unroll
        for (int tt = 0; tt < 8; tt++) {
            int m = b * TSEQ + t0 + tt;
            float dtr = bd;
            #pragma unroll
            for (int r = 0; r < 16; r++) dtr += sp[tt][r] * W16[r];
            float dt = (dtr > 15.f) ? dtr : log1pf(__expf(dtr));
            float x = xc8[tt];
            float dtx = dt * x;

            float dA[16];
            if (lin) {
                // dA[n] = p^(n+1), p = exp(dt*A0); two 8-deep mul chains
                float p  = __expf(dt * A0);
                float p2 = p * p;
                float c1 = p, c2 = p2;
                dA[0] = c1; dA[1] = c2;
                #pragma unroll
                for (int j = 2; j < 16; j += 2) {
                    c1 *= p2; c2 *= p2;
                    dA[j] = c1; dA[j + 1] = c2;
                }
            } else {
                #pragma unroll
                for (int n = 0; n < 16; n++) dA[n] = __expf(dt * A[n]);
            }

            float y = 0.f;
            #pragma unroll
            for (int n = 0; n < 16; n++) {
                h[n] = dA[n] * h[n] + dtx * sp[tt][16 + n];
                y += h[n] * sp[tt][32 + n];
            }
            float z = z8[tt];
            float o = (y + x * Dd) * (z / (1.f + __expf(-z)));
            g_y[(size_t)m * DI + d] = o;
        }
    }
}

// ---------------- output heads ----------------
__global__ void k_heads(const float* __restrict__ ps_W, const float* __restrict__ ps_b,
                        const float* __restrict__ pa_W, const float* __restrict__ pa_b,
                        float* __restrict__ out)
{
    int idx = blockIdx.x * blockDim.x + threadIdx.x;
    if (idx >= 6144 + 3072) return;
    if (idx < 6144) {
        int j = idx % 6; int l = (idx / 6) % LQ; int b = idx / (6 * LQ);
        int m = b * TSEQ + l * 3 + 2;
        float acc = ps_b[j];
        const float* f = g_fin + (size_t)m * DM;
        #pragma unroll 8
        for (int e = 0; e < DM; e++) acc += f[e] * ps_W[e * 6 + j];
        out[idx] = acc;
    } else {
        int k = idx - 6144;
        int j = k % 3; int l = (k / 3) % LQ; int b = k / (3 * LQ);
        int m = b * TSEQ + l * 3 + 1;
        float acc = pa_b[j];
        const float* f = g_fin + (size_t)m * DM;
        #pragma unroll 8
        for (int e = 0; e < DM; e++) acc += f[e] * pa_W[e * 3 + j];
        out[idx] = tanhf(acc);
    }
}

// ---------------- launch ----------------
extern "C" void kernel_launch(void* const* d_in, const int* in_sizes, int n_in,
                              void* d_out, int out_size)
{
    const float* states    = (const float*)d_in[0];
    const float* actions   = (const float*)d_in[1];
    const float* goal      = (const float*)d_in[2];
    const int*   timesteps = (const int*)  d_in[3];
    const float* te_W      = (const float*)d_in[4];
    const float* se_W      = (const float*)d_in[5];
    const float* se_b      = (const float*)d_in[6];
    const float* ge_W      = (const float*)d_in[7];
    const float* ge_b      = (const float*)d_in[8];
    const float* ae_W      = (const float*)d_in[9];
    const float* ae_b      = (const float*)d_in[10];
    const float* bb_in_W   = (const float*)d_in[11];
    const float* bb_in_b   = (const float*)d_in[12];
    const float* norm_w    = (const float*)d_in[13];
    const float* in_proj_W = (const float*)d_in[14];
    const float* conv_w    = (const float*)d_in[15];
    const float* conv_b    = (const float*)d_in[16];
    const float* xproj_W   = (const float*)d_in[17];
    const float* dt_W      = (const float*)d_in[18];
    const float* dt_b      = (const float*)d_in[19];
    const float* A_log     = (const float*)d_in[20];
    const float* Dp        = (const float*)d_in[21];
    const float* out_W     = (const float*)d_in[22];
    const float* fnorm_w   = (const float*)d_in[23];
    const float* ps_W      = (const float*)d_in[24];
    const float* ps_b      = (const float*)d_in[25];
    const float* pa_W      = (const float*)d_in[26];
    const float* pa_b      = (const float*)d_in[27];
    float* out = (float*)d_out;

    float *pu, *pres, *prs, *pxz, *pxc, *pproj, *py, *pfin;
    cudaGetSymbolAddress((void**)&pu,    g_u);
    cudaGetSymbolAddress((void**)&pres,  g_res);
    cudaGetSymbolAddress((void**)&prs,   g_rs);
    cudaGetSymbolAddress((void**)&pxz,   g_xz);
    cudaGetSymbolAddress((void**)&pxc,   g_xc);
    cudaGetSymbolAddress((void**)&pproj, g_proj);
    cudaGetSymbolAddress((void**)&py,    g_y);
    cudaGetSymbolAddress((void**)&pfin,  g_fin);

    // 1) embeddings -> u
    k_embed<<<MTOK, DM>>>(states, actions, goal, timesteps, te_W,
                          se_W, se_b, ge_W, ge_b, ae_W, ae_b);

    // 2) residual = u @ bb_in_W + bb_in_b   (3072 x 256 x 256)
    k_gemm128<0, false><<<dim3(DM / 64, MTOK / 128, 1), 256>>>(
        pu, DM, bb_in_W, DM, DM, bb_in_b, nullptr, nullptr, pres, DM);

    // 3) mamba layers
    for (int i = 0; i < NL; i++) {
        const float* inW  = in_proj_W + (size_t)i * DM * 2 * DI;
        const float* cw   = conv_w    + (size_t)i * DI * 4;
        const float* cb   = conv_b    + (size_t)i * DI;
        const float* xpW  = xproj_W   + (size_t)i * DI * 48;
        const float* dtW  = dt_W      + (size_t)i * RK * DI;
        const float* dtb  = dt_b      + (size_t)i * DI;
        const float* Al   = A_log     + (size_t)i * DI * DS;
        const float* Dpi  = Dp        + (size_t)i * DI;
        const float* oW   = out_W     + (size_t)i * DI * DM;
        const float* nw   = norm_w    + (size_t)i * DM;

        // rmsnorm row scales
        k_rowscale<<<MTOK / 8, 256>>>(pres, prs);

        // xz = rmsnorm(res) @ in_W   (3072 x 1024 x 256), norm folded into A-load
        k_gemm128<0, true><<<dim3(2 * DI / 64, MTOK / 128, 1), 256>>>(
            pres, DM, inW, 2 * DI, DM, nullptr, prs, nw, pxz, 2 * DI);

        // causal depthwise conv + silu -> xc ; zero proj
        k_conv<<<((MTOK / 4) * (DI / 4)) / 256, 256>>>(cw, cb);

        // proj = xc @ xproj_W  (3072 x 48 x 512), split-K x4, atomic accumulate
        k_xproj<<<dim3(1, MTOK / 64, 4), 256>>>(pxc, DI, xpW, 48, DI / 4, pproj, 48);

        // selective scan (fused dt-GEMM + softplus + gate) -> y
        k_scan<<<BQ * 8, 64>>>(Al, Dpi, dtW, dtb);

        // residual += y @ out_W   (3072 x 256 x 512), split-K x2, atomic accumulate
        k_gemm128<2, false><<<dim3(DM / 64, MTOK / 128, 2), 256>>>(
            py, DI, oW, DM, DI / 2, nullptr, nullptr, nullptr, pres, DM);
    }

    // 4) final norm + heads
    k_rmsnorm<<<MTOK, DM>>>(pres, fnorm_w, pfin);
    k_heads<<<(9216 + 255) / 256, 256>>>(ps_W, ps_b, pa_W, pa_b, out);
}

// round 11
// speedup vs baseline: 1.8155x; 1.0841x over previous
#include <cuda_runtime.h>
#include <math.h>

// ---------------- problem constants ----------------
#define BQ   8
#define LQ   128
#define TSEQ 384          // 3 * L tokens per batch
#define MTOK 3072         // BQ * TSEQ
#define DM   256          // d_model
#define DI   512          // d_inner
#define DS   16           // d_state
#define RK   16           // dt_rank
#define NL   4

// ---------------- scratch (device globals; no allocation allowed) ----------------
__device__ float g_u  [MTOK * DM];
__device__ float g_res[MTOK * DM];
__device__ float g_rs [MTOK];          // per-row rmsnorm scales
__device__ float g_xz [MTOK * 2 * DI];
__device__ float g_xc [MTOK * DI];
__device__ float g_proj[MTOK * 48];
__device__ float g_y  [MTOK * DI];

// ---------------- embeddings + interleave -> u ----------------
__global__ void k_embed(const float* __restrict__ states,
                        const float* __restrict__ actions,
                        const float* __restrict__ goal,
                        const int*   __restrict__ timesteps,
                        const float* __restrict__ te_W,
                        const float* __restrict__ se_W, const float* __restrict__ se_b,
                        const float* __restrict__ ge_W, const float* __restrict__ ge_b,
                        const float* __restrict__ ae_W, const float* __restrict__ ae_b)
{
    int m = blockIdx.x;          // token 0..3071
    int e = threadIdx.x;         // 0..255
    int b = m / TSEQ, t = m % TSEQ;
    int slot = t % 3, l = t / 3;

    const float *inp, *Wm, *bi; int dim;
    if (slot == 0)      { inp = goal;    Wm = ge_W; bi = ge_b; dim = 6; }
    else if (slot == 1) { inp = states;  Wm = se_W; bi = se_b; dim = 6; }
    else                { inp = actions; Wm = ae_W; bi = ae_b; dim = 3; }

    float v = bi[e];
    const float* ip = inp + (size_t)(b * LQ + l) * dim;
    #pragma unroll 6
    for (int i = 0; i < dim; i++) v += ip[i] * Wm[i * DM + e];

    int ts = timesteps[b * LQ + l];
    v += te_W[(size_t)ts * DM + e];
    g_u[(size_t)m * DM + e] = v;
}

// ---------------- per-row rmsnorm scale: rs[m] = rsqrt(mean(x^2)+eps) ----------------
__global__ void k_rowscale(const float* __restrict__ in, float* __restrict__ rs)
{
    int warp = blockIdx.x * 8 + (threadIdx.x >> 5);
    int lane = threadIdx.x & 31;
    const float4* p = (const float4*)(in + (size_t)warp * DM);
    float s = 0.f;
    #pragma unroll
    for (int i = lane; i < DM / 4; i += 32) {
        float4 v = p[i];
        s += v.x * v.x + v.y * v.y + v.z * v.z + v.w * v.w;
    }
    #pragma unroll
    for (int o = 16; o > 0; o >>= 1) s += __shfl_down_sync(0xffffffffu, s, o);
    if (lane == 0) rs[warp] = rsqrtf(s * (1.0f / DM) + 1e-5f);
}

// ---------------- 128x64x16 SGEMM, 8x4 per thread, float4 everywhere ----------------
// C[M,N] = A'[M,K] @ W[K,N]  where A' = A (NORM=false) or A * rs[m] * nw[k] (NORM=true)
// EPI: 0 = store (+bias if non-null), 1 = accumulate into C, 2 = atomicAdd (split-K)
// K is the K-slice length; blockIdx.z selects the slice.
template<int EPI, bool NORM>
__global__ __launch_bounds__(256)
void k_gemm128(const float* __restrict__ A, int lda,
               const float* __restrict__ W, int N, int K,
               const float* __restrict__ bias,
               const float* __restrict__ rs,
               const float* __restrict__ nw,
               float* __restrict__ C, int ldc)
{
    __shared__ float As[16][128];
    __shared__ float Ws[16][68];

    int tid = threadIdx.x;
    int bm = blockIdx.y * 128, bn = blockIdx.x * 64;
    int kb = blockIdx.z * K;
    int tx = tid & 15;       // col group -> cols tx*4 .. +4
    int ty = tid >> 4;       // row group -> rows ty*8 .. +8

    int arow = tid >> 2;            // 0..63
    int acol = (tid & 3) * 4;       // 0,4,8,12
    int wk = tid >> 4, wn = (tid & 15) * 4;

    float s0 = 1.f, s1 = 1.f;
    if (NORM) {
        s0 = rs[bm + arow];
        s1 = rs[bm + arow + 64];
    }

    const float* Ap0 = A + (size_t)(bm + arow) * lda + kb + acol;
    const float* Ap1 = Ap0 + (size_t)64 * lda;

    float4 pa0 = *(const float4*)(Ap0);
    float4 pa1 = *(const float4*)(Ap1);
    float4 pw  = *(const float4*)(W + (size_t)(kb + wk) * N + bn + wn);

    float acc[8][4] = {};

    for (int k0 = 0; k0 < K; k0 += 16) {
        __syncthreads();
        if (NORM) {
            float n0 = nw[k0 + acol + 0], n1 = nw[k0 + acol + 1];
            float n2 = nw[k0 + acol + 2], n3 = nw[k0 + acol + 3];
            As[acol + 0][arow] = pa0.x * s0 * n0;
            As[acol + 1][arow] = pa0.y * s0 * n1;
            As[acol + 2][arow] = pa0.z * s0 * n2;
            As[acol + 3][arow] = pa0.w * s0 * n3;
            As[acol + 0][arow + 64] = pa1.x * s1 * n0;
            As[acol + 1][arow + 64] = pa1.y * s1 * n1;
            As[acol + 2][arow + 64] = pa1.z * s1 * n2;
            As[acol + 3][arow + 64] = pa1.w * s1 * n3;
        } else {
            As[acol + 0][arow] = pa0.x;
            As[acol + 1][arow] = pa0.y;
            As[acol + 2][arow] = pa0.z;
            As[acol + 3][arow] = pa0.w;
            As[acol + 0][arow + 64] = pa1.x;
            As[acol + 1][arow + 64] = pa1.y;
            As[acol + 2][arow + 64] = pa1.z;
            As[acol + 3][arow + 64] = pa1.w;
        }
        *(float4*)&Ws[wk][wn] = pw;
        __syncthreads();

        if (k0 + 16 < K) {
            pa0 = *(const float4*)(Ap0 + k0 + 16);
            pa1 = *(const float4*)(Ap1 + k0 + 16);
            pw  = *(const float4*)(W + (size_t)(kb + k0 + 16 + wk) * N + bn + wn);
        }

        #pragma unroll
        for (int k = 0; k < 16; k++) {
            float4 a0 = *(const float4*)&As[k][ty * 8];
            float4 a1 = *(const float4*)&As[k][ty * 8 + 4];
            float4 w0 = *(const float4*)&Ws[k][tx * 4];
            float a[8] = {a0.x, a0.y, a0.z, a0.w, a1.x, a1.y, a1.z, a1.w};
            float w[4] = {w0.x, w0.y, w0.z, w0.w};
            #pragma unroll
            for (int i = 0; i < 8; i++)
                #pragma unroll
                for (int j = 0; j < 4; j++) acc[i][j] += a[i] * w[j];
        }
    }

    #pragma unroll
    for (int i = 0; i < 8; i++) {
        int row = bm + ty * 8 + i;
        #pragma unroll
        for (int j = 0; j < 4; j++) {
            int col = bn + tx * 4 + j;
            float v = acc[i][j];
            if (EPI == 0) {
                if (bias) v += bias[col];
                C[(size_t)row * ldc + col] = v;
            } else if (EPI == 1) {
                C[(size_t)row * ldc + col] += v;
            } else {
                atomicAdd(&C[(size_t)row * ldc + col], v);
            }
        }
    }
}

// ---------------- 64x64 split-K SGEMM (xproj, N=48), atomic epilogue ----------
__global__ __launch_bounds__(256)
void k_xproj(const float* __restrict__ A, int lda,
             const float* __restrict__ W, int N, int Ks,
             float* __restrict__ C, int ldc)
{
    __shared__ float As[16][64];
    __shared__ float Ws[16][68];

    int tid = threadIdx.x;
    int tx = tid & 15, ty = tid >> 4;
    int bm = blockIdx.y * 64, bn = blockIdx.x * 64;
    int kb = blockIdx.z * Ks;
    int arow = tid >> 2, acol = (tid & 3) << 2;
    int wn = tx * 4;
    bool wok = (bn + wn) < N;

    const float* Arow = A + (size_t)(bm + arow) * lda + acol;
    float4 pa = *(const float4*)(Arow + kb);
    float4 pw = make_float4(0.f, 0.f, 0.f, 0.f);
    if (wok) pw = *(const float4*)(W + (size_t)(kb + ty) * N + bn + wn);

    float acc[4][4] = {};

    for (int k0 = kb; k0 < kb + Ks; k0 += 16) {
        __syncthreads();
        As[acol + 0][arow] = pa.x;
        As[acol + 1][arow] = pa.y;
        As[acol + 2][arow] = pa.z;
        As[acol + 3][arow] = pa.w;
        *(float4*)&Ws[ty][wn] = pw;
        __syncthreads();

        if (k0 + 16 < kb + Ks) {
            pa = *(const float4*)(Arow + k0 + 16);
            if (wok) pw = *(const float4*)(W + (size_t)(k0 + 16 + ty) * N + bn + wn);
        }

        #pragma unroll
        for (int k = 0; k < 16; k++) {
            float4 a0 = *(const float4*)&As[k][ty * 4];
            float4 w0 = *(const float4*)&Ws[k][tx * 4];
            float a[4] = {a0.x, a0.y, a0.z, a0.w};
            float w[4] = {w0.x, w0.y, w0.z, w0.w};
            #pragma unroll
            for (int i = 0; i < 4; i++)
                #pragma unroll
                for (int j = 0; j < 4; j++) acc[i][j] += a[i] * w[j];
        }
    }

    #pragma unroll
    for (int i = 0; i < 4; i++) {
        int row = bm + ty * 4 + i;
        #pragma unroll
        for (int j = 0; j < 4; j++) {
            int col = bn + tx * 4 + j;
            if (col < N) atomicAdd(&C[(size_t)row * ldc + col], acc[i][j]);
        }
    }
}

// ---------------- causal depthwise conv (k=4) + silu, 4 tokens/thread ----------
// Also zeroes g_proj for the split-K xproj that follows.
__global__ void k_conv(const float* __restrict__ cw, const float* __restrict__ cb)
{
    int idx = blockIdx.x * blockDim.x + threadIdx.x;  // over (MTOK/4)*(DI/4)=98304
    {
        if (idx < MTOK * 48) g_proj[idx] = 0.f;
        int i2 = idx + 98304;
        if (i2 < MTOK * 48) g_proj[i2] = 0.f;
    }
    if (idx >= (MTOK / 4) * (DI / 4)) return;
    int mg = idx / (DI / 4), dv = idx % (DI / 4);
    int d = dv * 4;
    int b = mg / (TSEQ / 4), tg = mg % (TSEQ / 4);
    int t0 = tg * 4;

    float4 win[7];
    #pragma unroll
    for (int j = 0; j < 7; j++) {
        int tt = t0 - 3 + j;
        win[j] = (tt >= 0)
            ? *(const float4*)(g_xz + (size_t)(b * TSEQ + tt) * (2 * DI) + d)
            : make_float4(0.f, 0.f, 0.f, 0.f);
    }

    float4 cw0 = *(const float4*)(cw + (d + 0) * 4);
    float4 cw1 = *(const float4*)(cw + (d + 1) * 4);
    float4 cw2 = *(const float4*)(cw + (d + 2) * 4);
    float4 cw3 = *(const float4*)(cw + (d + 3) * 4);
    float4 cb4 = *(const float4*)(cb + d);

    float cwk[4][4] = {{cw0.x, cw0.y, cw0.z, cw0.w},
                       {cw1.x, cw1.y, cw1.z, cw1.w},
                       {cw2.x, cw2.y, cw2.z, cw2.w},
                       {cw3.x, cw3.y, cw3.z, cw3.w}};

    #pragma unroll
    for (int j2 = 0; j2 < 4; j2++) {
        float4 acc = cb4;
        #pragma unroll
        for (int k = 0; k < 4; k++) {
            float4 v = win[j2 + k];
            acc.x += cwk[0][k] * v.x;
            acc.y += cwk[1][k] * v.y;
            acc.z += cwk[2][k] * v.z;
            acc.w += cwk[3][k] * v.w;
        }
        acc.x = acc.x / (1.f + __expf(-acc.x));
        acc.y = acc.y / (1.f + __expf(-acc.y));
        acc.z = acc.z / (1.f + __expf(-acc.z));
        acc.w = acc.w / (1.f + __expf(-acc.w));
        *(float4*)(g_xc + (size_t)(b * TSEQ + t0 + j2) * DI + d) = acc;
    }
}

// ---------------- selective scan: recurrence-only serial loop -----------------
// Per 8-step chunk: dt/softplus/exp/silu/D-skip all precomputed with full ILP;
// the serial loop is just h[n] = dA[n]*h[n] + dtx*B[n]; y += h[n]*C[n].
__global__ __launch_bounds__(64)
void k_scan(const float* __restrict__ A_log, const float* __restrict__ Dp,
            const float* __restrict__ dtW, const float* __restrict__ dtb)
{
    int b = blockIdx.x >> 3;                          // batch
    int d = ((blockIdx.x & 7) << 6) + threadIdx.x;    // 0..511

    float A[16], h[16];
    #pragma unroll
    for (int n = 0; n < 16; n++) {
        A[n] = -__expf(A_log[d * 16 + n]);
        h[n] = 0.f;
    }
    // Detect linear spectrum A[n] = (n+1)*A[0]  (true for this model's A_log).
    float A0 = A[0];
    bool lin = true;
    #pragma unroll
    for (int n = 0; n < 16; n++)
        lin = lin && (fabsf(A[n] - (float)(n + 1) * A0) <= 1e-4f * fabsf(A[n]));

    float W16[16];
    #pragma unroll
    for (int r = 0; r < 16; r++) W16[r] = dtW[r * DI + d];
    float bd = dtb[d], Dd = Dp[d];

    __shared__ float sp[8][48];   // 8 steps of (dt_in[16], B[16], C[16])

    for (int t0 = 0; t0 < TSEQ; t0 += 8) {
        __syncthreads();
        int i0 = threadIdx.x * 6;                     // 64*6 = 384 floats
        #pragma unroll
        for (int i = 0; i < 6; i++) {
            int idx = i0 + i; int st = idx / 48, j = idx % 48;
            sp[st][j] = g_proj[((size_t)(b * TSEQ + t0 + st)) * 48 + j];
        }
        // batch-prefetch xc and z for the 8 steps (16 independent loads)
        float xc8[8], z8[8];
        #pragma unroll
        for (int i = 0; i < 8; i++)
            xc8[i] = g_xc[(size_t)(b * TSEQ + t0 + i) * DI + d];
        #pragma unroll
        for (int i = 0; i < 8; i++)
            z8[i] = g_xz[(size_t)(b * TSEQ + t0 + i) * (2 * DI) + DI + d];
        __syncthreads();

        // ---- precompute (independent across tt, full ILP) ----
        float dtx8[8], p8[8], gz8[8], xD8[8];
        #pragma unroll
        for (int tt = 0; tt < 8; tt++) {
            float dtr = bd;
            #pragma unroll
            for (int r = 0; r < 16; r++) dtr += sp[tt][r] * W16[r];
            float dt = (dtr > 15.f) ? dtr : log1pf(__expf(dtr));
            float x = xc8[tt];
            dtx8[tt] = dt * x;
            p8[tt] = lin ? __expf(dt * A0) : dt;      // !lin: keep dt for fallback
            float z = z8[tt];
            gz8[tt] = z / (1.f + __expf(-z));
            xD8[tt] = x * Dd;
        }

        // ---- serial recurrence (h-FMA only on the chain) ----
        #pragma unroll
        for (int tt = 0; tt < 8; tt++) {
            float dA[16];
            if (lin) {
                float p = p8[tt], p2 = p * p;
                float c1 = p, c2 = p2;
                dA[0] = c1; dA[1] = c2;
                #pragma unroll
                for (int j = 2; j < 16; j += 2) {
                    c1 *= p2; c2 *= p2;
                    dA[j] = c1; dA[j + 1] = c2;
                }
            } else {
                #pragma unroll
                for (int n = 0; n < 16; n++) dA[n] = __expf(p8[tt] * A[n]);
            }

            float dtx = dtx8[tt];
            float y0 = 0.f, y1 = 0.f, y2 = 0.f, y3 = 0.f;
            #pragma unroll
            for (int n = 0; n < 16; n += 4) {
                h[n + 0] = dA[n + 0] * h[n + 0] + dtx * sp[tt][16 + n + 0];
                h[n + 1] = dA[n + 1] * h[n + 1] + dtx * sp[tt][16 + n + 1];
                h[n + 2] = dA[n + 2] * h[n + 2] + dtx * sp[tt][16 + n + 2];
                h[n + 3] = dA[n + 3] * h[n + 3] + dtx * sp[tt][16 + n + 3];
                y0 += h[n + 0] * sp[tt][32 + n + 0];
                y1 += h[n + 1] * sp[tt][32 + n + 1];
                y2 += h[n + 2] * sp[tt][32 + n + 2];
                y3 += h[n + 3] * sp[tt][32 + n + 3];
            }
            float y = (y0 + y1) + (y2 + y3);
            g_y[(size_t)(b * TSEQ + t0 + tt) * DI + d] = (y + xD8[tt]) * gz8[tt];
        }
    }
}

// ---------------- heads with fused final rmsnorm (via rs) ----------------
__global__ void k_heads(const float* __restrict__ fnw, const float* __restrict__ rs,
                        const float* __restrict__ ps_W, const float* __restrict__ ps_b,
                        const float* __restrict__ pa_W, const float* __restrict__ pa_b,
                        float* __restrict__ out)
{
    int idx = blockIdx.x * blockDim.x + threadIdx.x;
    if (idx >= 6144 + 3072) return;
    if (idx < 6144) {
        int j = idx % 6; int l = (idx / 6) % LQ; int b = idx / (6 * LQ);
        int m = b * TSEQ + l * 3 + 2;   // action-slot tokens -> state preds
        float acc = 0.f;
        const float* f = g_res + (size_t)m * DM;
        #pragma unroll 8
        for (int e = 0; e < DM; e++) acc += f[e] * fnw[e] * ps_W[e * 6 + j];
        out[idx] = acc * rs[m] + ps_b[j];
    } else {
        int k = idx - 6144;
        int j = k % 3; int l = (k / 3) % LQ; int b = k / (3 * LQ);
        int m = b * TSEQ + l * 3 + 1;   // state-slot tokens -> action preds
        float acc = 0.f;
        const float* f = g_res + (size_t)m * DM;
        #pragma unroll 8
        for (int e = 0; e < DM; e++) acc += f[e] * fnw[e] * pa_W[e * 3 + j];
        out[idx] = tanhf(acc * rs[m] + pa_b[j]);
    }
}

// ---------------- launch ----------------
extern "C" void kernel_launch(void* const* d_in, const int* in_sizes, int n_in,
                              void* d_out, int out_size)
{
    const float* states    = (const float*)d_in[0];
    const float* actions   = (const float*)d_in[1];
    const float* goal      = (const float*)d_in[2];
    const int*   timesteps = (const int*)  d_in[3];
    const float* te_W      = (const float*)d_in[4];
    const float* se_W      = (const float*)d_in[5];
    const float* se_b      = (const float*)d_in[6];
    const float* ge_W      = (const float*)d_in[7];
    const float* ge_b      = (const float*)d_in[8];
    const float* ae_W      = (const float*)d_in[9];
    const float* ae_b      = (const float*)d_in[10];
    const float* bb_in_W   = (const float*)d_in[11];
    const float* bb_in_b   = (const float*)d_in[12];
    const float* norm_w    = (const float*)d_in[13];
    const float* in_proj_W = (const float*)d_in[14];
    const float* conv_w    = (const float*)d_in[15];
    const float* conv_b    = (const float*)d_in[16];
    const float* xproj_W   = (const float*)d_in[17];
    const float* dt_W      = (const float*)d_in[18];
    const float* dt_b      = (const float*)d_in[19];
    const float* A_log     = (const float*)d_in[20];
    const float* Dp        = (const float*)d_in[21];
    const float* out_W     = (const float*)d_in[22];
    const float* fnorm_w   = (const float*)d_in[23];
    const float* ps_W      = (const float*)d_in[24];
    const float* ps_b      = (const float*)d_in[25];
    const float* pa_W      = (const float*)d_in[26];
    const float* pa_b      = (const float*)d_in[27];
    float* out = (float*)d_out;

    float *pu, *pres, *prs, *pxz, *pxc, *pproj, *py;
    cudaGetSymbolAddress((void**)&pu,    g_u);
    cudaGetSymbolAddress((void**)&pres,  g_res);
    cudaGetSymbolAddress((void**)&prs,   g_rs);
    cudaGetSymbolAddress((void**)&pxz,   g_xz);
    cudaGetSymbolAddress((void**)&pxc,   g_xc);
    cudaGetSymbolAddress((void**)&pproj, g_proj);
    cudaGetSymbolAddress((void**)&py,    g_y);

    // 1) embeddings -> u
    k_embed<<<MTOK, DM>>>(states, actions, goal, timesteps, te_W,
                          se_W, se_b, ge_W, ge_b, ae_W, ae_b);

    // 2) residual = u @ bb_in_W + bb_in_b   (3072 x 256 x 256)
    k_gemm128<0, false><<<dim3(DM / 64, MTOK / 128, 1), 256>>>(
        pu, DM, bb_in_W, DM, DM, bb_in_b, nullptr, nullptr, pres, DM);

    // 3) mamba layers
    for (int i = 0; i < NL; i++) {
        const float* inW  = in_proj_W + (size_t)i * DM * 2 * DI;
        const float* cw   = conv_w    + (size_t)i * DI * 4;
        const float* cb   = conv_b    + (size_t)i * DI;
        const float* xpW  = xproj_W   + (size_t)i * DI * 48;
        const float* dtW  = dt_W      + (size_t)i * RK * DI;
        const float* dtb  = dt_b      + (size_t)i * DI;
        const float* Al   = A_log     + (size_t)i * DI * DS;
        const float* Dpi  = Dp        + (size_t)i * DI;
        const float* oW   = out_W     + (size_t)i * DI * DM;
        const float* nw   = norm_w    + (size_t)i * DM;

        // rmsnorm row scales
        k_rowscale<<<MTOK / 8, 256>>>(pres, prs);

        // xz = rmsnorm(res) @ in_W   (3072 x 1024 x 256), norm folded into A-load
        k_gemm128<0, true><<<dim3(2 * DI / 64, MTOK / 128, 1), 256>>>(
            pres, DM, inW, 2 * DI, DM, nullptr, prs, nw, pxz, 2 * DI);

        // causal depthwise conv + silu -> xc ; zero proj
        k_conv<<<((MTOK / 4) * (DI / 4)) / 256, 256>>>(cw, cb);

        // proj = xc @ xproj_W  (3072 x 48 x 512), split-K x4, atomic accumulate
        k_xproj<<<dim3(1, MTOK / 64, 4), 256>>>(pxc, DI, xpW, 48, DI / 4, pproj, 48);

        // selective scan (fused dt-GEMM + softplus + gate) -> y
        k_scan<<<BQ * 8, 64>>>(Al, Dpi, dtW, dtb);

        // residual += y @ out_W   (3072 x 256 x 512), split-K x2, atomic accumulate
        k_gemm128<2, false><<<dim3(DM / 64, MTOK / 128, 2), 256>>>(
            py, DI, oW, DM, DI / 2, nullptr, nullptr, nullptr, pres, DM);
    }

    // 4) final rmsnorm scales + fused heads
    k_rowscale<<<MTOK / 8, 256>>>(pres, prs);
    k_heads<<<(9216 + 255) / 256, 256>>>(fnorm_w, prs, ps_W, ps_b, pa_W, pa_b, out);
}